// round 4
// baseline (speedup 1.0000x reference)
#include <cuda_runtime.h>

#define D_IN   187
#define H_HID  50
#define C_OUT  5
#define TPB    128
#define TCH    5      // time-chunk length
#define DC     47     // d-chunk for x staging (odd -> conflict-free shared stride)
#define THR    1.0f
#define BETA   0.9f

// Dynamic shared layout (floats):
//  [0,                D_IN*52)        : W1 transposed, [d][h], row pitch 52 (16B aligned)
//  [D_IN*52,          +H_HID*8)       : W2 as [h][8] (c in 0..4), 16B aligned rows
//  [.. ,              +TPB*DC)        : x staging tile [row][dl], stride DC
#define SM_W1   0
#define SM_W2   (D_IN * 52)
#define SM_X    (SM_W2 + H_HID * 8)
#define SM_FLOATS (SM_X + TPB * DC)
#define SMEM_BYTES (SM_FLOATS * 4)

__global__ __launch_bounds__(TPB)
void snn_fused_kernel(const float* __restrict__ x,
                      const float* __restrict__ W1,
                      const float* __restrict__ b1,
                      const float* __restrict__ W2,
                      const float* __restrict__ b2,
                      float* __restrict__ out,
                      int B, int steps)
{
    extern __shared__ float smem[];
    float* sW1 = smem + SM_W1;
    float* sW2 = smem + SM_W2;
    float* sx  = smem + SM_X;

    const int tid = threadIdx.x;
    const int b   = blockIdx.x * TPB + tid;

    // ---- stage weights into shared ----
    for (int i = tid; i < D_IN * H_HID; i += TPB) {
        int d = i / H_HID;
        int h = i - d * H_HID;
        sW1[d * 52 + h] = W1[h * D_IN + d];
    }
    for (int i = tid; i < H_HID * C_OUT; i += TPB) {
        int h = i % H_HID;
        int c = i / H_HID;
        sW2[h * 8 + c] = W2[c * H_HID + h];
    }

    // ---- phase 1: cur1 = (x @ W1^T) + b1 ----
    // Ascending-k single-accumulator fp32 fma chain (empirically matches the
    // reference GEMM rounding, R2/R3 evidence), bias added as a SEPARATE
    // rounded add afterwards.
    float cur1[H_HID];
#pragma unroll
    for (int h = 0; h < H_HID; ++h) cur1[h] = 0.0f;

    for (int d0 = 0; d0 < D_IN; d0 += DC) {
        const int len = (D_IN - d0 < DC) ? (D_IN - d0) : DC;
        __syncthreads();
        for (int i = tid; i < TPB * len; i += TPB) {
            int r  = i / len;
            int dl = i - r * len;
            int gr = blockIdx.x * TPB + r;
            sx[r * DC + dl] = (gr < B) ? x[(size_t)gr * D_IN + d0 + dl] : 0.0f;
        }
        __syncthreads();
        for (int dl = 0; dl < len; ++dl) {
            const float xv = sx[tid * DC + dl];
            const float* wr = &sW1[(d0 + dl) * 52];
#pragma unroll
            for (int h4 = 0; h4 < 48; h4 += 4) {
                float4 w = *(const float4*)(wr + h4);
                cur1[h4 + 0] = fmaf(w.x, xv, cur1[h4 + 0]);
                cur1[h4 + 1] = fmaf(w.y, xv, cur1[h4 + 1]);
                cur1[h4 + 2] = fmaf(w.z, xv, cur1[h4 + 2]);
                cur1[h4 + 3] = fmaf(w.w, xv, cur1[h4 + 3]);
            }
            cur1[48] = fmaf(wr[48], xv, cur1[48]);
            cur1[49] = fmaf(wr[49], xv, cur1[49]);
        }
    }
#pragma unroll
    for (int h = 0; h < H_HID; ++h) cur1[h] = __fadd_rn(cur1[h], b1[h]);

    // ---- phase 2: time loop, chunked by TCH ----
    float mem1[H_HID];
#pragma unroll
    for (int h = 0; h < H_HID; ++h) mem1[h] = 0.0f;

    float mem2[C_OUT];
    float rb2[C_OUT];
#pragma unroll
    for (int c = 0; c < C_OUT; ++c) { mem2[c] = 0.0f; rb2[c] = b2[c]; }

    const size_t memoff = (size_t)steps * B * C_OUT;
    const bool valid = (b < B);

    for (int tc = 0; tc < steps; tc += TCH) {
        // c2 accumulates the spk1 @ W2^T dot from ZERO (ascending h);
        // b2 added separately at consumption time.
        float c2[TCH][C_OUT];
#pragma unroll
        for (int ti = 0; ti < TCH; ++ti)
#pragma unroll
            for (int c = 0; c < C_OUT; ++c) c2[ti][c] = 0.0f;

        // hidden layer: h outer (W2 regs cached per chunk), t inner.
        // identity: reset_{t+1} == spike_t == (mem1_t > THR)
        // Recurrence: FUSED multiply-add (XLA fusion emits fma.rn), then a
        // separate subtract: m = fma(BETA, m, cur1) - reset.
#pragma unroll
        for (int h = 0; h < H_HID; ++h) {
            float m  = mem1[h];
            const float c1 = cur1[h];
            const float4 wv = *(const float4*)&sW2[h * 8];
            const float w4  = sW2[h * 8 + 4];
            float r = (m > THR) ? 1.0f : 0.0f;   // reset from current mem
#pragma unroll
            for (int ti = 0; ti < TCH; ++ti) {
                m = __fsub_rn(fmaf(BETA, m, c1), r);
                r = (m > THR) ? 1.0f : 0.0f;      // spike(t) == reset(t+1)
                c2[ti][0] = fmaf(r, wv.x, c2[ti][0]);
                c2[ti][1] = fmaf(r, wv.y, c2[ti][1]);
                c2[ti][2] = fmaf(r, wv.z, c2[ti][2]);
                c2[ti][3] = fmaf(r, wv.w, c2[ti][3]);
                c2[ti][4] = fmaf(r, w4,  c2[ti][4]);
            }
            mem1[h] = m;
        }

        // output layer + stores
#pragma unroll
        for (int ti = 0; ti < TCH; ++ti) {
            const int t = tc + ti;
            const bool wr = valid && (t < steps);
            const size_t ob = (size_t)t * B * C_OUT + (size_t)b * C_OUT;
#pragma unroll
            for (int c = 0; c < C_OUT; ++c) {
                const float cur2 = __fadd_rn(c2[ti][c], rb2[c]);  // dot + b2
                float m2 = mem2[c];
                const float r2 = (m2 > THR) ? 1.0f : 0.0f;
                m2 = __fsub_rn(fmaf(BETA, m2, cur2), r2);
                mem2[c] = m2;
                const float s2 = (m2 > THR) ? 1.0f : 0.0f;
                if (wr) {
                    out[ob + c]          = s2;   // spk_rec
                    out[memoff + ob + c] = m2;   // mem_rec
                }
            }
        }
    }
}

extern "C" void kernel_launch(void* const* d_in, const int* in_sizes, int n_in,
                              void* d_out, int out_size)
{
    const float* x  = (const float*)d_in[0];
    const float* W1 = (const float*)d_in[1];
    const float* b1 = (const float*)d_in[2];
    const float* W2 = (const float*)d_in[3];
    const float* b2 = (const float*)d_in[4];
    float* out = (float*)d_out;

    const int B = in_sizes[0] / D_IN;
    const int steps = (int)((long long)out_size / (2LL * B * C_OUT));

    cudaFuncSetAttribute(snn_fused_kernel,
                         cudaFuncAttributeMaxDynamicSharedMemorySize, SMEM_BYTES);

    const int grid = (B + TPB - 1) / TPB;
    snn_fused_kernel<<<grid, TPB, SMEM_BYTES>>>(x, W1, b1, W2, b2, out, B, steps);
}

// round 5
// speedup vs baseline: 1.5090x; 1.5090x over previous
#include <cuda_runtime.h>

#define D_IN   187
#define H_HID  50
#define C_OUT  5
#define LPR    4            // lanes per row (h-split + time-skew relay)
#define HP     13           // h per lane (50 padded to 52)
#define TPB    128
#define RPB    (TPB/LPR)    // 32 rows per block
#define DC     47           // x staging chunk (odd -> conflict-free)
#define THR    1.0f
#define BETA   0.9f

// Shared layout (floats):
//  sW1: [d][j][20]  addr = d*80 + j*20 + i  (i<13 used; 20-pitch -> conflict-free float4)
//  sW2: [h][8]      h padded to 52 with zeros
//  sx : [row][DC]
#define W1_PITCH_D 80
#define SM_W1   0
#define SM_W1_SZ (D_IN * W1_PITCH_D)
#define SM_W2   (SM_W1 + SM_W1_SZ)
#define SM_W2_SZ (52 * 8)
#define SM_X    (SM_W2 + SM_W2_SZ)
#define SM_X_SZ (RPB * DC)
#define SMEM_BYTES ((SM_X + SM_X_SZ) * 4)

__global__ __launch_bounds__(TPB)
void snn_fused_kernel(const float* __restrict__ x,
                      const float* __restrict__ W1,
                      const float* __restrict__ b1,
                      const float* __restrict__ W2,
                      const float* __restrict__ b2,
                      float* __restrict__ out,
                      int B, int steps)
{
    extern __shared__ float smem[];
    float* sW1 = smem + SM_W1;
    float* sW2 = smem + SM_W2;
    float* sx  = smem + SM_X;

    const int tid   = threadIdx.x;
    const int j     = tid & (LPR - 1);      // lane role within row
    const int rloc  = tid >> 2;             // row within block
    const int row   = blockIdx.x * RPB + rloc;
    const bool rowv = (row < B);
    const int hbase = j * HP;

    // ---- stage W1 into [d][j][20] (h>=50 zero-padded) ----
    for (int idx = tid; idx < D_IN * 52; idx += TPB) {
        int d = idx / 52, h = idx - d * 52;
        float v = (h < H_HID) ? W1[h * D_IN + d] : 0.0f;
        sW1[d * W1_PITCH_D + (h / HP) * 20 + (h % HP)] = v;
    }
    // ---- stage W2 into [h][8] (h>=50 zero-padded) ----
    for (int idx = tid; idx < 52 * C_OUT; idx += TPB) {
        int h = idx % 52, c = idx / 52;
        sW2[h * 8 + c] = (h < H_HID) ? W2[c * H_HID + h] : 0.0f;
    }

    // ---- phase 1: cur1[h] for this lane's 13 h's; exact ascending-k fma chain ----
    float cur1[HP];
#pragma unroll
    for (int hh = 0; hh < HP; ++hh) cur1[hh] = 0.0f;

    for (int d0 = 0; d0 < D_IN; d0 += DC) {
        const int len = (D_IN - d0 < DC) ? (D_IN - d0) : DC;
        __syncthreads();   // also covers W1/W2 staging on first pass
        for (int i2 = tid; i2 < RPB * len; i2 += TPB) {
            int r  = i2 / len;
            int dl = i2 - r * len;
            int gr = blockIdx.x * RPB + r;
            sx[r * DC + dl] = (gr < B) ? x[(size_t)gr * D_IN + d0 + dl] : 0.0f;
        }
        __syncthreads();
        for (int dl = 0; dl < len; ++dl) {
            const float xv = sx[rloc * DC + dl];
            const float* wp = &sW1[(d0 + dl) * W1_PITCH_D + j * 20];
            float4 wa = *(const float4*)(wp + 0);
            float4 wb = *(const float4*)(wp + 4);
            float4 wc = *(const float4*)(wp + 8);
            float  wd = wp[12];
            cur1[0]  = fmaf(wa.x, xv, cur1[0]);
            cur1[1]  = fmaf(wa.y, xv, cur1[1]);
            cur1[2]  = fmaf(wa.z, xv, cur1[2]);
            cur1[3]  = fmaf(wa.w, xv, cur1[3]);
            cur1[4]  = fmaf(wb.x, xv, cur1[4]);
            cur1[5]  = fmaf(wb.y, xv, cur1[5]);
            cur1[6]  = fmaf(wb.z, xv, cur1[6]);
            cur1[7]  = fmaf(wb.w, xv, cur1[7]);
            cur1[8]  = fmaf(wc.x, xv, cur1[8]);
            cur1[9]  = fmaf(wc.y, xv, cur1[9]);
            cur1[10] = fmaf(wc.z, xv, cur1[10]);
            cur1[11] = fmaf(wc.w, xv, cur1[11]);
            cur1[12] = fmaf(wd,   xv, cur1[12]);
        }
    }
    // bias: separate rounded add (reference epilogue); dead h -> 0
#pragma unroll
    for (int hh = 0; hh < HP; ++hh) {
        int h = hbase + hh;
        if (h < H_HID) cur1[hh] = __fadd_rn(cur1[hh], b1[h]);
        else           cur1[hh] = 0.0f;
    }

    // ---- W2 columns for this lane's h's, fully register-resident ----
    float w2r[HP][C_OUT];
#pragma unroll
    for (int hh = 0; hh < HP; ++hh)
#pragma unroll
        for (int c = 0; c < C_OUT; ++c)
            w2r[hh][c] = sW2[(hbase + hh) * 8 + c];

    // ---- phase 2: time-skewed relay pipeline ----
    // Lane j processes step t = i - j. cur2's 50-term chain stays EXACTLY
    // serial: lane j continues the fma chain from lane j-1's partial
    // (received via shfl), so the result is bit-identical to one thread
    // accumulating h = 0..49 in order.
    float mem1[HP];
#pragma unroll
    for (int hh = 0; hh < HP; ++hh) mem1[hh] = 0.0f;

    float P[C_OUT] = {0, 0, 0, 0, 0};   // my partial c2 (output of my segment)
    float mem2[C_OUT], rb2[C_OUT];
#pragma unroll
    for (int c = 0; c < C_OUT; ++c) { mem2[c] = 0.0f; rb2[c] = b2[c]; }

    const size_t memoff = (size_t)steps * B * C_OUT;
    const int iters = steps + LPR - 1;

    for (int i = 0; i < iters; ++i) {
        // relay handoff (all lanes participate every iteration)
        float cin[C_OUT];
#pragma unroll
        for (int c = 0; c < C_OUT; ++c)
            cin[c] = __shfl_up_sync(0xFFFFFFFFu, P[c], 1, LPR);

        const int t = i - j;
        if (t >= 0 && t < steps) {
            float acc[C_OUT];
#pragma unroll
            for (int c = 0; c < C_OUT; ++c)
                acc[c] = (j == 0) ? 0.0f : cin[c];

#pragma unroll
            for (int hh = 0; hh < HP; ++hh) {
                float m = mem1[hh];
                const float r = (m > THR) ? 1.0f : 0.0f;   // reset from prev mem
                m = __fsub_rn(fmaf(BETA, m, cur1[hh]), r);
                mem1[hh] = m;
                const float s = (m > THR) ? 1.0f : 0.0f;   // spike
                acc[0] = fmaf(s, w2r[hh][0], acc[0]);
                acc[1] = fmaf(s, w2r[hh][1], acc[1]);
                acc[2] = fmaf(s, w2r[hh][2], acc[2]);
                acc[3] = fmaf(s, w2r[hh][3], acc[3]);
                acc[4] = fmaf(s, w2r[hh][4], acc[4]);
            }
#pragma unroll
            for (int c = 0; c < C_OUT; ++c) P[c] = acc[c];

            if (j == LPR - 1 && rowv) {
                const size_t ob = (size_t)t * B * C_OUT + (size_t)row * C_OUT;
#pragma unroll
                for (int c = 0; c < C_OUT; ++c) {
                    const float cur2 = __fadd_rn(P[c], rb2[c]);   // dot + b2
                    float m2 = mem2[c];
                    const float r2 = (m2 > THR) ? 1.0f : 0.0f;
                    m2 = __fsub_rn(fmaf(BETA, m2, cur2), r2);
                    mem2[c] = m2;
                    out[ob + c]          = (m2 > THR) ? 1.0f : 0.0f;  // spk_rec
                    out[memoff + ob + c] = m2;                         // mem_rec
                }
            }
        }
    }
}

extern "C" void kernel_launch(void* const* d_in, const int* in_sizes, int n_in,
                              void* d_out, int out_size)
{
    const float* x  = (const float*)d_in[0];
    const float* W1 = (const float*)d_in[1];
    const float* b1 = (const float*)d_in[2];
    const float* W2 = (const float*)d_in[3];
    const float* b2 = (const float*)d_in[4];
    float* out = (float*)d_out;

    const int B = in_sizes[0] / D_IN;
    const int steps = (int)((long long)out_size / (2LL * B * C_OUT));

    cudaFuncSetAttribute(snn_fused_kernel,
                         cudaFuncAttributeMaxDynamicSharedMemorySize, SMEM_BYTES);

    const int grid = (B + RPB - 1) / RPB;
    snn_fused_kernel<<<grid, TPB, SMEM_BYTES>>>(x, W1, b1, W2, b2, out, B, steps);
}